// round 12
// baseline (speedup 1.0000x reference)
#include <cuda_runtime.h>
#include <math_constants.h>
#include <cstdint>

// ---------------------------------------------------------------------------
// ReinforceDistributed: replicate JAX reference bit-exactly.
//   scores = per-split softmax of Linear(3,1) logits  (splits: 2048,1024,1024)
//   samples[e,b] = argmax_j ( log(scores[b,j]) + gumbel(key=42)[e,b,j] ), e=0..9
//   best[b] = argmax_j scores[b,j]
//   out[b]  = any_e(samples[e,b]==best[b]) ? best[b] : samples[9,b]
//
// ROUND NOTE: R0/R6/R10 all returned rel_err == 1.000000e+00 EXACTLY across
// three independent PRNG counter modes. Only consistent explanation: harness
// compares d_out as FLOAT32 and my int32 writes read as denormals ~ 0
// -> ||0 - ref||/||ref|| == 1.0 identically. Fix: write float action values.
// PRNG stays at the modern-JAX default: partitionable mode,
// bits = out0 ^ out1 of threefry2x32(key=(0,42), counts=(0, linear_index)).
//
// uniform: bitcast((bits>>9)|0x3f800000)-1, clamped at FLT_MIN.
// argmax(logp+g) == argmin(E*q) with E=-log(u), q=1/p  -> prune with the exact
// bound -ln u >= 1-u, evaluate survivors in XLA float space for exact ties.
// ---------------------------------------------------------------------------

#define JAX_PARTITIONABLE 1   // 1 = jax>=0.4.36 default; 0 = original split-iota

constexpr int   BATCH = 8192;
constexpr int   HALL  = 4096;
constexpr int   EPS   = 10;
constexpr unsigned BH = 33554432u;           // BATCH*HALL
constexpr float TINYF = 1.17549435e-38f;     // FLT_MIN (np.finfo(float32).tiny)

// scratch (no allocations allowed)
__device__ float g_q [BATCH * HALL];   // 1/p
__device__ float g_lp[BATCH * HALL];   // logf(p), exactly as XLA computes log(scores)
__device__ int   g_best[BATCH];
__device__ int   g_samp[EPS * BATCH];

// ------------------------- threefry2x32, key = (0, 42) ---------------------
__device__ __forceinline__ void tf2x32(unsigned v0, unsigned v1,
                                       unsigned& o0, unsigned& o1) {
  const unsigned KS0 = 0u, KS1 = 42u, KS2 = 0x1BD11BDAu ^ KS0 ^ KS1;
  unsigned x0 = v0 + KS0, x1 = v1 + KS1;
#define TFR(r) { x0 += x1; x1 = __funnelshift_l(x1, x1, (r)); x1 ^= x0; }
  TFR(13) TFR(15) TFR(26) TFR(6)
  x0 += KS1; x1 += KS2 + 1u;
  TFR(17) TFR(29) TFR(16) TFR(24)
  x0 += KS2; x1 += KS0 + 2u;
  TFR(13) TFR(15) TFR(26) TFR(6)
  x0 += KS0; x1 += KS1 + 3u;
  TFR(17) TFR(29) TFR(16) TFR(24)
  x0 += KS1; x1 += KS2 + 4u;
  TFR(13) TFR(15) TFR(26) TFR(6)
  x0 += KS2; x1 += KS0 + 5u;
#undef TFR
  o0 = x0; o1 = x1;
}

__device__ __forceinline__ unsigned tf_bits(unsigned i) {
#if JAX_PARTITIONABLE
  unsigned o0, o1;
  tf2x32(0u, i, o0, o1);   // (x0,x1) = (counts_hi, counts_lo) = (0, i)
  return o0 ^ o1;          // jax>=0.4.36 bit_width<=32 combine
#else
  // original mode: x = split(iota(N), 2); bind(k1,k2,x[0],x[1]); concat(out)
  const unsigned HALF = (unsigned)(EPS / 2) * BH;   // N/2 = 167772160
  unsigned o0, o1;
  if (i < HALF) { tf2x32(i, i + HALF, o0, o1); return o0; }
  else          { tf2x32(i - HALF, i, o0, o1); return o1; }
#endif
}

__device__ __forceinline__ float u_from_bits(unsigned bits) {
  // XLA: bitcast((bits>>9)|0x3f800000)-1.0 ; *(1-tiny)+tiny ; max(tiny, .)
  // which reduces exactly to max(u, tiny) in f32 (1-tiny rounds to 1.0f).
  float f = __uint_as_float((bits >> 9) | 0x3f800000u) - 1.0f;
  return fmaxf(f, TINYF);
}

// ------------------------- phase 1: scores -> q, logp, best -----------------
__global__ void __launch_bounds__(512) phase1(const float* __restrict__ X,
                                              const float* __restrict__ W,
                                              const float* __restrict__ bvec) {
  const int b   = blockIdx.x;
  const int tid = threadIdx.x;
  __shared__ float sl[HALL];
  __shared__ float sred[512];
  __shared__ int   sredi[512];

  float w[9];
#pragma unroll
  for (int k = 0; k < 9; ++k) w[k] = W[k];
  const float bb0 = bvec[0], bb1 = bvec[1], bb2 = bvec[2];

  const float* xr = X + (long long)b * (HALL * 3);

  // logits: splits are contiguous -> column base is simply 3*j
  for (int j = tid; j < HALL; j += 512) {
    const float* xp = xr + 3 * j;
    float x0 = xp[0], x1 = xp[1], x2 = xp[2];
    float l;
    if (j < 2048)      l = fmaf(x2, w[2], fmaf(x1, w[1], x0 * w[0])) + bb0;
    else if (j < 3072) l = fmaf(x2, w[5], fmaf(x1, w[4], x0 * w[3])) + bb1;
    else               l = fmaf(x2, w[8], fmaf(x1, w[7], x0 * w[6])) + bb2;
    sl[j] = l;
  }
  __syncthreads();

  // per-split max (max is order-independent -> exact match with XLA)
  float m[3];
#pragma unroll
  for (int d = 0; d < 3; ++d) {
    const int js = (d == 0) ? 0 : (d == 1 ? 2048 : 3072);
    const int je = (d == 0) ? 2048 : (d == 1 ? 3072 : 4096);
    float pm = -CUDART_INF_F;
    for (int j = js + tid; j < je; j += 512) pm = fmaxf(pm, sl[j]);
    sred[tid] = pm;
    __syncthreads();
    for (int s = 256; s > 0; s >>= 1) {
      if (tid < s) sred[tid] = fmaxf(sred[tid], sred[tid + s]);
      __syncthreads();
    }
    m[d] = sred[0];
    __syncthreads();
  }

  // exp + per-split sums
  float S[3];
#pragma unroll
  for (int d = 0; d < 3; ++d) {
    const int js = (d == 0) ? 0 : (d == 1 ? 2048 : 3072);
    const int je = (d == 0) ? 2048 : (d == 1 ? 3072 : 4096);
    float ps = 0.0f;
    for (int j = js + tid; j < je; j += 512) {
      float e = expf(sl[j] - m[d]);
      sl[j] = e;
      ps += e;
    }
    sred[tid] = ps;
    __syncthreads();
    for (int s = 256; s > 0; s >>= 1) {
      if (tid < s) sred[tid] += sred[tid + s];
      __syncthreads();
    }
    S[d] = sred[0];
    __syncthreads();
  }

  // p = e/S (div.rn, like XLA); store q = 1/p and logp = logf(p); argmax p
  float pbest = -CUDART_INF_F; int jb = 0x7fffffff;
  for (int j = tid; j < HALL; j += 512) {
    const int d = (j < 2048) ? 0 : (j < 3072 ? 1 : 2);
    float p = sl[j] / S[d];
    const unsigned idx = ((unsigned)b << 12) + (unsigned)j;
    g_q [idx] = 1.0f / p;
    g_lp[idx] = logf(p);
    if (p > pbest) { pbest = p; jb = j; }   // increasing j -> first occurrence
  }
  sred[tid] = pbest; sredi[tid] = jb;
  __syncthreads();
  for (int s = 256; s > 0; s >>= 1) {
    if (tid < s) {
      float po = sred[tid + s]; int jo = sredi[tid + s];
      if (po > sred[tid] || (po == sred[tid] && jo < sredi[tid])) {
        sred[tid] = po; sredi[tid] = jo;
      }
    }
    __syncthreads();
  }
  if (tid == 0) g_best[b] = sredi[0];
}

// ------------------------- phase 2: gumbel-argmax per (e, b) ----------------
// one warp per (e,b): lanes stride j; prune via exact bound -ln u >= 1-u,
// survivors evaluated in XLA float space for exact comparison semantics.
__global__ void __launch_bounds__(256) phase2() {
  const int gw   = (blockIdx.x * 256 + threadIdx.x) >> 5;   // 0..81919
  const int lane = threadIdx.x & 31;
  const int e = gw >> 13;         // /8192
  const int b = gw & 8191;
  const float* __restrict__ qrow  = g_q  + ((unsigned)b << 12);
  const float* __restrict__ lprow = g_lp + ((unsigned)b << 12);
  const unsigned ibase = (unsigned)e * BH + ((unsigned)b << 12);

  float rmin  = CUDART_INF_F;    // running min of E*q (merged warp-wide periodically)
  float rthr  = CUDART_INF_F;    // prune threshold = rmin * (1+1e-4)
  float vbest = -CUDART_INF_F;   // exact XLA-space best
  int   jbest = 0x7fffffff;

#pragma unroll 4
  for (int t = 0; t < 128; ++t) {
    const int j = lane + (t << 5);
    const float qj = qrow[j];
    const unsigned bits = tf_bits(ibase + (unsigned)j);
    const float u  = u_from_bits(bits);
    const float lb = (1.0f - u) * qj;          // lower bound on E*q
    if (lb <= rthr) {
      const float lu = logf(u);                // == XLA log(u)
      const float E  = -lu;
      const float r  = E * qj;
      rmin = fminf(rmin, r);
      const float v = lprow[j] - logf(E);      // == logp + (-log(-log u)) bitwise
      if (v > vbest) { vbest = v; jbest = j; } // increasing j per lane -> first occ.
    }
    if ((t & 15) == 15) {
#pragma unroll
      for (int o = 16; o; o >>= 1)
        rmin = fminf(rmin, __shfl_xor_sync(0xffffffffu, rmin, o));
      rthr = rmin * 1.0001f;
    }
  }

  // warp argmax with first-occurrence tie-break
#pragma unroll
  for (int o = 16; o; o >>= 1) {
    float vo = __shfl_xor_sync(0xffffffffu, vbest, o);
    int   jo = __shfl_xor_sync(0xffffffffu, jbest, o);
    if (vo > vbest || (vo == vbest && jo < jbest)) { vbest = vo; jbest = jo; }
  }
  if (lane == 0) g_samp[gw] = jbest;
}

// ------------------------- phase 3: combine (FLOAT output) ------------------
__global__ void phase3(float* __restrict__ out) {
  const int b = blockIdx.x * blockDim.x + threadIdx.x;
  if (b >= BATCH) return;
  const int best = g_best[b];
  bool hit = false;
#pragma unroll
  for (int e = 0; e < EPS; ++e) hit = hit || (g_samp[e * BATCH + b] == best);
  const int action = hit ? best : g_samp[(EPS - 1) * BATCH + b];
  out[b] = (float)action;          // <-- output dtype fix: write float32
}

// ------------------------- launch -------------------------------------------
extern "C" void kernel_launch(void* const* d_in, const int* in_sizes, int n_in,
                              void* d_out, int out_size) {
  // size-based dispatch (robust to metadata ordering), positional fallback:
  //   X: 8192*12288 = 100663296, W: 9, b: 3
  const float* X  = nullptr; const float* W = nullptr; const float* bv = nullptr;
  for (int i = 0; i < n_in; ++i) {
    if      (in_sizes[i] == 100663296) X  = (const float*)d_in[i];
    else if (in_sizes[i] == 9)         W  = (const float*)d_in[i];
    else if (in_sizes[i] == 3)         bv = (const float*)d_in[i];
  }
  if (!X)  X  = (const float*)d_in[0];
  if (!W)  W  = (const float*)d_in[1];
  if (!bv) bv = (const float*)d_in[2];
  float* out = (float*)d_out;                // (8192,) float32

  phase1<<<BATCH, 512>>>(X, W, bv);
  phase2<<<(EPS * BATCH * 32) / 256, 256>>>();
  phase3<<<(BATCH + 255) / 256, 256>>>(out);
}

// round 15
// speedup vs baseline: 1.0849x; 1.0849x over previous
#include <cuda_runtime.h>
#include <math_constants.h>
#include <cstdint>

// ---------------------------------------------------------------------------
// ReinforceDistributed — bit-exact JAX replication (R12 PASSED, 1164.8us).
//   scores = per-split softmax (splits 2048,1024,1024); samples via gumbel
//   argmax with threefry2x32 key (0,42), partitionable mode, bits=out0^out1.
//
// R13 optimizations (correctness-preserving):
//  * phase1: float4-staged X in dynamic smem, shuffle reductions, store p only.
//  * phase2: logf(p) computed for survivors only (bitwise == stored-lp scheme);
//    prune with (2-f1) <= rthr*p  [1-u == 2-f1 exactly, Sterbenz];
//    chunk-0 peeled unconditional eval -> warm threshold immediately;
//    per-chunk warp rmin merge; threefry round-1 specialized for (0, i+42).
//  * Prune-safety: threshold = rmin*(1+1e-3); rmin only shrinks over time, so
//    pruning compares a lower bound (1-u <= E) against a value >= winner's r;
//    1e-3 margin >> all float slop (logf ~1e-7). Survivors evaluated in exact
//    XLA float space with explicit (v,j) tie-break.
// ---------------------------------------------------------------------------

constexpr int   BATCH = 8192;
constexpr int   HALL  = 4096;
constexpr int   EPS   = 10;
constexpr int   ROWF  = HALL * 3;            // 12288 floats per X row
constexpr unsigned BH = 33554432u;           // BATCH*HALL
constexpr float TINYF = 1.17549435e-38f;     // FLT_MIN

// scratch (no allocations allowed)
__device__ float g_p   [BATCH * HALL];   // softmax probs (e/S, div.rn like XLA)
__device__ int   g_best[BATCH];
__device__ int   g_samp[EPS * BATCH];

// ------------------- threefry2x32, key=(0,42), counts=(0,i) -----------------
// Specialized: KS0=0, KS1=42, KS2=0x1BD11BDA^42=0x1BD11BF0.
// init x0=0, x1=i+42; round1: x0+=x1 -> x0=a; x1=rotl(a,13)^a.
__device__ __forceinline__ unsigned tf_bits(unsigned a /* = i + 42 */) {
  const unsigned KS1 = 42u, KS2 = 0x1BD11BF0u;
  unsigned x0 = a;
  unsigned x1 = __funnelshift_l(a, a, 13) ^ a;
#define TFR(r) { x0 += x1; x1 = __funnelshift_l(x1, x1, (r)); x1 ^= x0; }
  TFR(15) TFR(26) TFR(6)
  x0 += KS1; x1 += KS2 + 1u;
  TFR(17) TFR(29) TFR(16) TFR(24)
  x0 += KS2; x1 += 2u;                 // KS0 = 0
  TFR(13) TFR(15) TFR(26) TFR(6)
  /* x0 += KS0 (=0) */ x1 += KS1 + 3u;
  TFR(17) TFR(29) TFR(16) TFR(24)
  x0 += KS1; x1 += KS2 + 4u;
  TFR(13) TFR(15) TFR(26) TFR(6)
  x0 += KS2; x1 += 5u;                 // KS0 + 5
#undef TFR
  return x0 ^ x1;                      // jax>=0.4.36 bit_width<=32 combine
}

// ------------------------- phase 1: X -> p, best ----------------------------
__global__ void __launch_bounds__(512) phase1(const float* __restrict__ X,
                                              const float* __restrict__ W,
                                              const float* __restrict__ bvec) {
  extern __shared__ float sx[];            // ROWF floats (48KB, dynamic)
  __shared__ float sredf[16 * 3];
  __shared__ float sb[3];
  __shared__ float spv[16];
  __shared__ int   spj[16];

  const int b    = blockIdx.x;
  const int tid  = threadIdx.x;
  const int wid  = tid >> 5;
  const int lane = tid & 31;

  // stage X row, fully coalesced float4
  {
    const float4* xv = (const float4*)(X + (long long)b * ROWF);
    float4* sxv = (float4*)sx;
    for (int i = tid; i < ROWF / 4; i += 512) sxv[i] = xv[i];
  }

  float w[9];
#pragma unroll
  for (int k = 0; k < 9; ++k) w[k] = W[k];
  float bb[3] = {bvec[0], bvec[1], bvec[2]};

  __syncthreads();

  // 8 logits per thread; j = tid + 512k -> split d is compile-time per k
  float lreg[8];
#pragma unroll
  for (int k = 0; k < 8; ++k) {
    const int j = tid + (k << 9);
    const int d = (k < 4) ? 0 : (k < 6 ? 1 : 2);
    float x0 = sx[3 * j], x1 = sx[3 * j + 1], x2 = sx[3 * j + 2];
    lreg[k] = fmaf(x2, w[3 * d + 2], fmaf(x1, w[3 * d + 1], x0 * w[3 * d])) + bb[d];
  }

  // per-split max: thread partials -> warp shuffle -> smem -> 3 threads
  {
    float pm[3] = {-CUDART_INF_F, -CUDART_INF_F, -CUDART_INF_F};
#pragma unroll
    for (int k = 0; k < 8; ++k) {
      const int d = (k < 4) ? 0 : (k < 6 ? 1 : 2);
      pm[d] = fmaxf(pm[d], lreg[k]);
    }
#pragma unroll
    for (int d = 0; d < 3; ++d)
#pragma unroll
      for (int o = 16; o; o >>= 1)
        pm[d] = fmaxf(pm[d], __shfl_xor_sync(0xffffffffu, pm[d], o));
    if (lane == 0) {
#pragma unroll
      for (int d = 0; d < 3; ++d) sredf[wid * 3 + d] = pm[d];
    }
  }
  __syncthreads();
  if (tid < 3) {
    float m = -CUDART_INF_F;
#pragma unroll
    for (int wdx = 0; wdx < 16; ++wdx) m = fmaxf(m, sredf[wdx * 3 + tid]);
    sb[tid] = m;
  }
  __syncthreads();
  const float m0 = sb[0], m1 = sb[1], m2 = sb[2];
  __syncthreads();   // protect sb before reuse

  // exp + per-split sums (keep e in registers)
  float ereg[8];
  {
    float ps[3] = {0.0f, 0.0f, 0.0f};
#pragma unroll
    for (int k = 0; k < 8; ++k) {
      const int d = (k < 4) ? 0 : (k < 6 ? 1 : 2);
      const float m = (d == 0) ? m0 : (d == 1 ? m1 : m2);
      float e = expf(lreg[k] - m);
      ereg[k] = e;
      ps[d] += e;
    }
#pragma unroll
    for (int d = 0; d < 3; ++d)
#pragma unroll
      for (int o = 16; o; o >>= 1)
        ps[d] += __shfl_xor_sync(0xffffffffu, ps[d], o);
    if (lane == 0) {
#pragma unroll
      for (int d = 0; d < 3; ++d) sredf[wid * 3 + d] = ps[d];
    }
  }
  __syncthreads();
  if (tid < 3) {
    float s = 0.0f;
#pragma unroll
    for (int wdx = 0; wdx < 16; ++wdx) s += sredf[wdx * 3 + tid];
    sb[tid] = s;
  }
  __syncthreads();
  const float S0 = sb[0], S1 = sb[1], S2 = sb[2];

  // p = e/S (div.rn like XLA); store p; argmax p with first-occurrence ties
  float pbest = -CUDART_INF_F; int jb = 0x7fffffff;
#pragma unroll
  for (int k = 0; k < 8; ++k) {
    const int j = tid + (k << 9);
    const int d = (k < 4) ? 0 : (k < 6 ? 1 : 2);
    const float S = (d == 0) ? S0 : (d == 1 ? S1 : S2);
    float p = ereg[k] / S;
    g_p[((unsigned)b << 12) + (unsigned)j] = p;
    if (p > pbest) { pbest = p; jb = j; }   // j increasing per thread
  }
#pragma unroll
  for (int o = 16; o; o >>= 1) {
    float po = __shfl_xor_sync(0xffffffffu, pbest, o);
    int   jo = __shfl_xor_sync(0xffffffffu, jb, o);
    if (po > pbest || (po == pbest && jo < jb)) { pbest = po; jb = jo; }
  }
  if (lane == 0) { spv[wid] = pbest; spj[wid] = jb; }
  __syncthreads();
  if (tid == 0) {
    float pv = spv[0]; int pj = spj[0];
#pragma unroll
    for (int wdx = 1; wdx < 16; ++wdx) {
      if (spv[wdx] > pv || (spv[wdx] == pv && spj[wdx] < pj)) { pv = spv[wdx]; pj = spj[wdx]; }
    }
    g_best[b] = pj;
  }
}

// ------------------------- phase 2: gumbel-argmax per (e, b) ----------------
// one warp per (e,b); lane handles 4 consecutive j per chunk (float4 p load).
__global__ void __launch_bounds__(256) phase2() {
  const int gw   = (blockIdx.x * 256 + threadIdx.x) >> 5;   // 0..81919
  const int lane = threadIdx.x & 31;
  const int e = gw >> 13;
  const int b = gw & 8191;
  const float* __restrict__ prow = g_p + ((unsigned)b << 12);
  const unsigned ib42 = (unsigned)e * BH + ((unsigned)b << 12) + 42u;

  float rmin  = CUDART_INF_F;
  float vbest = -CUDART_INF_F;
  int   jbest = 0x7fffffff;

  // ---- chunk 0 (peeled): unconditional exact eval to warm the threshold ----
  {
    const int j0 = lane << 2;
    const float4 pv = *(const float4*)(prow + j0);
#pragma unroll
    for (int k = 0; k < 4; ++k) {
      const int j = j0 + k;
      const float p = (k == 0) ? pv.x : (k == 1) ? pv.y : (k == 2) ? pv.z : pv.w;
      const unsigned bits = tf_bits(ib42 + (unsigned)j);
      const float f1 = __uint_as_float((bits >> 9) | 0x3f800000u);
      const float u  = fmaxf(f1 - 1.0f, TINYF);
      const float E  = -logf(u);
      rmin = fminf(rmin, E / p);
      const float v = logf(p) - logf(E);       // bitwise == logp + gumbel cmp space
      if (v > vbest || (v == vbest && j < jbest)) { vbest = v; jbest = j; }
    }
  }
#pragma unroll
  for (int o = 16; o; o >>= 1)
    rmin = fminf(rmin, __shfl_xor_sync(0xffffffffu, rmin, o));
  float rthr = rmin * 1.001f;

  // ---- chunks 1..31: prune with (2-f1) <= rthr*p, exact eval survivors -----
  for (int c = 1; c < 32; ++c) {
    const int j0 = (c << 7) + (lane << 2);
    const float4 pv = *(const float4*)(prow + j0);
#pragma unroll
    for (int k = 0; k < 4; ++k) {
      const int j = j0 + k;
      const float p = (k == 0) ? pv.x : (k == 1) ? pv.y : (k == 2) ? pv.z : pv.w;
      const unsigned bits = tf_bits(ib42 + (unsigned)j);
      const float f1  = __uint_as_float((bits >> 9) | 0x3f800000u);
      const float omu = 2.0f - f1;             // == 1-u exactly (u = f1-1)
      if (omu <= rthr * p) {
        const float u = fmaxf(f1 - 1.0f, TINYF);
        const float E = -logf(u);
        rmin = fminf(rmin, E / p);
        const float v = logf(p) - logf(E);
        if (v > vbest || (v == vbest && j < jbest)) { vbest = v; jbest = j; }
      }
    }
#pragma unroll
    for (int o = 16; o; o >>= 1)
      rmin = fminf(rmin, __shfl_xor_sync(0xffffffffu, rmin, o));
    rthr = rmin * 1.001f;
  }

  // warp argmax with first-occurrence tie-break
#pragma unroll
  for (int o = 16; o; o >>= 1) {
    float vo = __shfl_xor_sync(0xffffffffu, vbest, o);
    int   jo = __shfl_xor_sync(0xffffffffu, jbest, o);
    if (vo > vbest || (vo == vbest && jo < jbest)) { vbest = vo; jbest = jo; }
  }
  if (lane == 0) g_samp[gw] = jbest;
}

// ------------------------- phase 3: combine (float output) ------------------
__global__ void phase3(float* __restrict__ out) {
  const int b = blockIdx.x * blockDim.x + threadIdx.x;
  if (b >= BATCH) return;
  const int best = g_best[b];
  bool hit = false;
#pragma unroll
  for (int e = 0; e < EPS; ++e) hit = hit || (g_samp[e * BATCH + b] == best);
  const int action = hit ? best : g_samp[(EPS - 1) * BATCH + b];
  out[b] = (float)action;
}

// ------------------------- launch -------------------------------------------
extern "C" void kernel_launch(void* const* d_in, const int* in_sizes, int n_in,
                              void* d_out, int out_size) {
  const float* X  = nullptr; const float* W = nullptr; const float* bv = nullptr;
  for (int i = 0; i < n_in; ++i) {
    if      (in_sizes[i] == BATCH * ROWF) X  = (const float*)d_in[i];
    else if (in_sizes[i] == 9)            W  = (const float*)d_in[i];
    else if (in_sizes[i] == 3)            bv = (const float*)d_in[i];
  }
  if (!X)  X  = (const float*)d_in[0];
  if (!W)  W  = (const float*)d_in[1];
  if (!bv) bv = (const float*)d_in[2];
  float* out = (float*)d_out;

  const int smem1 = ROWF * (int)sizeof(float);   // 48KB dynamic
  cudaFuncSetAttribute(phase1, cudaFuncAttributeMaxDynamicSharedMemorySize, smem1);

  phase1<<<BATCH, 512, smem1>>>(X, W, bv);
  phase2<<<(EPS * BATCH * 32) / 256, 256>>>();
  phase3<<<(BATCH + 255) / 256, 256>>>(out);
}

// round 16
// speedup vs baseline: 1.1101x; 1.0231x over previous
#include <cuda_runtime.h>
#include <math_constants.h>
#include <cstdint>

// ---------------------------------------------------------------------------
// ReinforceDistributed — bit-exact JAX replication. R15 PASSED @1073.6us
// (phase1 119.7, phase2 ~950). R16: FUSE all phases into one kernel:
//   block b: softmax p -> SMEM (16KB); warps 0..9 run the full gumbel scan
//   for e=warp (identical math to R15 phase2, p via LDS.128); thread 0
//   combines and writes out[b].
// Removes: 134MB p store + 1.34GB p re-reads + phase3 + launch gaps; overlaps
// the 402MB X DRAM stream with other blocks' ALU-bound hashing.
//
// Exactness (unchanged from R15, rel_err 0.0):
//  * p = e/S with div.rn, same bits as XLA softmax.
//  * threefry2x32 key (0,42), partitionable counters (0,i), bits = o0^o1.
//  * u = max(bitcast((bits>>9)|0x3f800000)-1, FLT_MIN).
//  * argmax(logp+g) == argmin(E/p); prune with exact bound 1-u <= E:
//    skip j only if (1-u_j) > rthr*p_j, rthr = rmin*1.001, rmin a true min of
//    evaluated r = E/p (chunk-0 evaluated unconditionally). Margin 1e-3 >>
//    float slop. Survivors compared in exact XLA float space
//    v = logf(p) - logf(E), first-occurrence tie-breaks everywhere.
// ---------------------------------------------------------------------------

constexpr int   BATCH = 8192;
constexpr int   HALL  = 4096;
constexpr int   EPS   = 10;
constexpr int   ROWF  = HALL * 3;            // 12288 floats per X row
constexpr unsigned BH = 33554432u;           // BATCH*HALL
constexpr float TINYF = 1.17549435e-38f;     // FLT_MIN

// ------------------- threefry2x32, key=(0,42), counts=(0,i) -----------------
// Specialized: KS0=0, KS1=42, KS2=0x1BD11BDA^42=0x1BD11BF0.
// init x0=0, x1=i+42; round1: x0+=x1 -> x0=a; x1=rotl(a,13)^a.
__device__ __forceinline__ unsigned tf_bits(unsigned a /* = i + 42 */) {
  const unsigned KS1 = 42u, KS2 = 0x1BD11BF0u;
  unsigned x0 = a;
  unsigned x1 = __funnelshift_l(a, a, 13) ^ a;
#define TFR(r) { x0 += x1; x1 = __funnelshift_l(x1, x1, (r)); x1 ^= x0; }
  TFR(15) TFR(26) TFR(6)
  x0 += KS1; x1 += KS2 + 1u;
  TFR(17) TFR(29) TFR(16) TFR(24)
  x0 += KS2; x1 += 2u;                 // KS0 = 0
  TFR(13) TFR(15) TFR(26) TFR(6)
  /* x0 += KS0 (=0) */ x1 += KS1 + 3u;
  TFR(17) TFR(29) TFR(16) TFR(24)
  x0 += KS1; x1 += KS2 + 4u;
  TFR(13) TFR(15) TFR(26) TFR(6)
  x0 += KS2; x1 += 5u;                 // KS0 + 5
#undef TFR
  return x0 ^ x1;                      // jax>=0.4.36 bit_width<=32 combine
}

// ------------------------- fused kernel -------------------------------------
__global__ void __launch_bounds__(512) fused(const float* __restrict__ X,
                                             const float* __restrict__ W,
                                             const float* __restrict__ bvec,
                                             float* __restrict__ out) {
  __shared__ float sp[HALL];               // softmax probs (16KB)
  __shared__ float sredf[16 * 3];
  __shared__ float sb[3];
  __shared__ float spv[16];
  __shared__ int   spj[16];
  __shared__ int   s_best;
  __shared__ int   s_samp[EPS];

  const int b    = blockIdx.x;
  const int tid  = threadIdx.x;
  const int wid  = tid >> 5;
  const int lane = tid & 31;

  // ==================== phase 1: softmax -> sp, best ========================
  {
    float w[9];
#pragma unroll
    for (int k = 0; k < 9; ++k) w[k] = W[k];
    float bb[3] = {bvec[0], bvec[1], bvec[2]};

    const float* xr = X + (long long)b * ROWF;

    // 8 logits per thread; j = tid + 512k (consecutive tid -> consecutive j:
    // warp touches contiguous 384B = 3 full lines per k -> DRAM-optimal)
    float lreg[8];
#pragma unroll
    for (int k = 0; k < 8; ++k) {
      const int j = tid + (k << 9);
      const int d = (k < 4) ? 0 : (k < 6 ? 1 : 2);
      const float* xp = xr + 3 * j;
      float x0 = xp[0], x1 = xp[1], x2 = xp[2];
      lreg[k] = fmaf(x2, w[3 * d + 2], fmaf(x1, w[3 * d + 1], x0 * w[3 * d])) + bb[d];
    }

    // per-split max: thread partials -> warp shuffle -> smem -> 3 threads
    {
      float pm[3] = {-CUDART_INF_F, -CUDART_INF_F, -CUDART_INF_F};
#pragma unroll
      for (int k = 0; k < 8; ++k) {
        const int d = (k < 4) ? 0 : (k < 6 ? 1 : 2);
        pm[d] = fmaxf(pm[d], lreg[k]);
      }
#pragma unroll
      for (int d = 0; d < 3; ++d)
#pragma unroll
        for (int o = 16; o; o >>= 1)
          pm[d] = fmaxf(pm[d], __shfl_xor_sync(0xffffffffu, pm[d], o));
      if (lane == 0) {
#pragma unroll
        for (int d = 0; d < 3; ++d) sredf[wid * 3 + d] = pm[d];
      }
    }
    __syncthreads();
    if (tid < 3) {
      float m = -CUDART_INF_F;
#pragma unroll
      for (int wdx = 0; wdx < 16; ++wdx) m = fmaxf(m, sredf[wdx * 3 + tid]);
      sb[tid] = m;
    }
    __syncthreads();
    const float m0 = sb[0], m1 = sb[1], m2 = sb[2];
    __syncthreads();   // protect sb before reuse

    // exp + per-split sums
    float ereg[8];
    {
      float ps[3] = {0.0f, 0.0f, 0.0f};
#pragma unroll
      for (int k = 0; k < 8; ++k) {
        const int d = (k < 4) ? 0 : (k < 6 ? 1 : 2);
        const float m = (d == 0) ? m0 : (d == 1 ? m1 : m2);
        float e = expf(lreg[k] - m);
        ereg[k] = e;
        ps[d] += e;
      }
#pragma unroll
      for (int d = 0; d < 3; ++d)
#pragma unroll
        for (int o = 16; o; o >>= 1)
          ps[d] += __shfl_xor_sync(0xffffffffu, ps[d], o);
      if (lane == 0) {
#pragma unroll
        for (int d = 0; d < 3; ++d) sredf[wid * 3 + d] = ps[d];
      }
    }
    __syncthreads();
    if (tid < 3) {
      float s = 0.0f;
#pragma unroll
      for (int wdx = 0; wdx < 16; ++wdx) s += sredf[wdx * 3 + tid];
      sb[tid] = s;
    }
    __syncthreads();
    const float S0 = sb[0], S1 = sb[1], S2 = sb[2];

    // p = e/S (div.rn like XLA); store to SMEM; argmax with first-occ ties
    float pbest = -CUDART_INF_F; int jb = 0x7fffffff;
#pragma unroll
    for (int k = 0; k < 8; ++k) {
      const int j = tid + (k << 9);
      const int d = (k < 4) ? 0 : (k < 6 ? 1 : 2);
      const float S = (d == 0) ? S0 : (d == 1 ? S1 : S2);
      float p = ereg[k] / S;
      sp[j] = p;
      if (p > pbest) { pbest = p; jb = j; }
    }
#pragma unroll
    for (int o = 16; o; o >>= 1) {
      float po = __shfl_xor_sync(0xffffffffu, pbest, o);
      int   jo = __shfl_xor_sync(0xffffffffu, jb, o);
      if (po > pbest || (po == pbest && jo < jb)) { pbest = po; jb = jo; }
    }
    if (lane == 0) { spv[wid] = pbest; spj[wid] = jb; }
  }
  __syncthreads();   // sp[] complete + spv/spj complete
  if (tid == 0) {
    float pv = spv[0]; int pj = spj[0];
#pragma unroll
    for (int wdx = 1; wdx < 16; ++wdx) {
      if (spv[wdx] > pv || (spv[wdx] == pv && spj[wdx] < pj)) { pv = spv[wdx]; pj = spj[wdx]; }
    }
    s_best = pj;
  }

  // ==================== phase 2: gumbel argmax, warp e = wid ================
  if (wid < EPS) {
    const int e = wid;
    const unsigned ib42 = (unsigned)e * BH + ((unsigned)b << 12) + 42u;

    float rmin  = CUDART_INF_F;
    float vbest = -CUDART_INF_F;
    int   jbest = 0x7fffffff;

    // ---- chunk 0 (peeled): unconditional exact eval to warm the threshold --
    {
      const int j0 = lane << 2;
      const float4 pv = *(const float4*)(sp + j0);
#pragma unroll
      for (int k = 0; k < 4; ++k) {
        const int j = j0 + k;
        const float p = (k == 0) ? pv.x : (k == 1) ? pv.y : (k == 2) ? pv.z : pv.w;
        const unsigned bits = tf_bits(ib42 + (unsigned)j);
        const float f1 = __uint_as_float((bits >> 9) | 0x3f800000u);
        const float u  = fmaxf(f1 - 1.0f, TINYF);
        const float E  = -logf(u);
        rmin = fminf(rmin, E / p);
        const float v = logf(p) - logf(E);     // exact XLA comparison space
        if (v > vbest || (v == vbest && j < jbest)) { vbest = v; jbest = j; }
      }
    }
#pragma unroll
    for (int o = 16; o; o >>= 1)
      rmin = fminf(rmin, __shfl_xor_sync(0xffffffffu, rmin, o));
    float rthr = rmin * 1.001f;

    // ---- chunks 1..31: prune with (2-f1) <= rthr*p, exact eval survivors ---
    for (int c = 1; c < 32; ++c) {
      const int j0 = (c << 7) + (lane << 2);
      const float4 pv = *(const float4*)(sp + j0);
#pragma unroll
      for (int k = 0; k < 4; ++k) {
        const int j = j0 + k;
        const float p = (k == 0) ? pv.x : (k == 1) ? pv.y : (k == 2) ? pv.z : pv.w;
        const unsigned bits = tf_bits(ib42 + (unsigned)j);
        const float f1  = __uint_as_float((bits >> 9) | 0x3f800000u);
        const float omu = 2.0f - f1;           // == 1-u exactly (Sterbenz)
        if (omu <= rthr * p) {
          const float u = fmaxf(f1 - 1.0f, TINYF);
          const float E = -logf(u);
          rmin = fminf(rmin, E / p);
          const float v = logf(p) - logf(E);
          if (v > vbest || (v == vbest && j < jbest)) { vbest = v; jbest = j; }
        }
      }
#pragma unroll
      for (int o = 16; o; o >>= 1)
        rmin = fminf(rmin, __shfl_xor_sync(0xffffffffu, rmin, o));
      rthr = rmin * 1.001f;
    }

    // warp argmax with first-occurrence tie-break
#pragma unroll
    for (int o = 16; o; o >>= 1) {
      float vo = __shfl_xor_sync(0xffffffffu, vbest, o);
      int   jo = __shfl_xor_sync(0xffffffffu, jbest, o);
      if (vo > vbest || (vo == vbest && jo < jbest)) { vbest = vo; jbest = jo; }
    }
    if (lane == 0) s_samp[e] = jbest;
  }

  // ==================== phase 3: combine, write out[b] ======================
  __syncthreads();
  if (tid == 0) {
    const int best = s_best;
    bool hit = false;
#pragma unroll
    for (int e = 0; e < EPS; ++e) hit = hit || (s_samp[e] == best);
    const int action = hit ? best : s_samp[EPS - 1];
    out[b] = (float)action;
  }
}

// ------------------------- launch -------------------------------------------
extern "C" void kernel_launch(void* const* d_in, const int* in_sizes, int n_in,
                              void* d_out, int out_size) {
  const float* X  = nullptr; const float* W = nullptr; const float* bv = nullptr;
  for (int i = 0; i < n_in; ++i) {
    if      (in_sizes[i] == BATCH * ROWF) X  = (const float*)d_in[i];
    else if (in_sizes[i] == 9)            W  = (const float*)d_in[i];
    else if (in_sizes[i] == 3)            bv = (const float*)d_in[i];
  }
  if (!X)  X  = (const float*)d_in[0];
  if (!W)  W  = (const float*)d_in[1];
  if (!bv) bv = (const float*)d_in[2];
  float* out = (float*)d_out;

  fused<<<BATCH, 512>>>(X, W, bv, out);
}